// round 4
// baseline (speedup 1.0000x reference)
#include <cuda_runtime.h>
#include <cuda_bf16.h>
#include <math.h>

// ---------------- problem constants (from reference setup) ----------------
#define MAXN 50000
#define MAXE 800000
#define D12  256      // H*HID for layers 1,2

// ---------------- scratch (device globals; referenced ONLY inside device code
// via compile-time-fixed symbol references) ---------------------------------
__device__ float g_bufA[MAXN * D12];   // h (post-GEMM)
__device__ float g_bufB[MAXN * D12];   // aggregated output
__device__ float g_als[MAXN * 4];
__device__ float g_ald[MAXN * 4];
__device__ float g_prow[MAXN * 64];
__device__ float g_pcol[MAXN * 64];
__device__ int g_deg[MAXN];
__device__ int g_off[MAXN + 1];
__device__ int g_cur[MAXN];
__device__ int g_csr[MAXE];

// ---------------- CSR construction ----------------
__global__ void zero_deg_kernel(int n) {
    int i = blockIdx.x * blockDim.x + threadIdx.x;
    if (i < n) g_deg[i] = 0;
}

// NOTE: edge_index is int32 (JAX x64 disabled demotes jnp.int64 -> int32).
__global__ void hist_kernel(const int* ei, int E) {
    int i = blockIdx.x * blockDim.x + threadIdx.x;
    if (i < E) atomicAdd(&g_deg[ei[E + i]], 1);
}

__global__ void scan_kernel(int n) {
    __shared__ int sh[1024];
    __shared__ int s_carry;
    int tid = threadIdx.x;
    if (tid == 0) s_carry = 0;
    __syncthreads();
    for (int base = 0; base < n; base += 1024) {
        int v = (base + tid < n) ? g_deg[base + tid] : 0;
        sh[tid] = v;
        __syncthreads();
        for (int o = 1; o < 1024; o <<= 1) {
            int t2 = (tid >= o) ? sh[tid - o] : 0;
            __syncthreads();
            sh[tid] += t2;
            __syncthreads();
        }
        int incl = sh[tid];
        int c = s_carry;
        int total = sh[1023];
        if (base + tid < n) {
            int e = c + incl - v;
            g_off[base + tid] = e;
            g_cur[base + tid] = e;
        }
        __syncthreads();
        if (tid == 0) s_carry = c + total;
        __syncthreads();
    }
    if (tid == 0) g_off[n] = s_carry;
}

__global__ void scatter_kernel(const int* ei, int E) {
    int i = blockIdx.x * blockDim.x + threadIdx.x;
    if (i < E) {
        int d = ei[E + i];
        int s = ei[i];
        int p = atomicAdd(&g_cur[d], 1);
        g_csr[p] = s;
    }
}

// ---------------- fp32 GEMM: C[M,Nc] = A[M,K] @ B[K,Nc] ----------------
// 64x64 tile, BK=16, 256 threads, 4x4 per thread. K%16==0, Nc%64==0 assumed.
// A source and C dest fixed at COMPILE TIME (no runtime pointer selects).
// ASYM: false -> A = Aext param; true -> A = g_bufB symbol.
// CSEL: 0 -> g_bufA, 1 -> g_prow, 2 -> g_pcol.
template <bool ASYM, int CSEL>
__global__ void gemm64_kernel(const float* Aext, const float* B, int M, int K, int Nc) {
    const float* A;
    if constexpr (ASYM) A = g_bufB; else A = Aext;
    float* C;
    if constexpr (CSEL == 0) C = g_bufA;
    else if constexpr (CSEL == 1) C = g_prow;
    else C = g_pcol;

    __shared__ float As[16][65];
    __shared__ float Bs[16][64];
    int bm = blockIdx.y * 64, bn = blockIdx.x * 64;
    int tid = threadIdx.x;
    int tx = tid & 15, ty = tid >> 4;
    int am = tid >> 2;
    int ak = (tid & 3) * 4;
    int bk = tid >> 4;
    int bn4 = (tid & 15) * 4;

    float acc[4][4];
#pragma unroll
    for (int i = 0; i < 4; i++)
#pragma unroll
        for (int j = 0; j < 4; j++) acc[i][j] = 0.f;

    for (int k0 = 0; k0 < K; k0 += 16) {
        float4 av = make_float4(0.f, 0.f, 0.f, 0.f);
        int arow = bm + am;
        if (arow < M) av = *(const float4*)(A + (size_t)arow * K + k0 + ak);
        As[ak + 0][am] = av.x;
        As[ak + 1][am] = av.y;
        As[ak + 2][am] = av.z;
        As[ak + 3][am] = av.w;
        float4 bv = *(const float4*)(B + (size_t)(k0 + bk) * Nc + bn + bn4);
        *(float4*)(&Bs[bk][bn4]) = bv;
        __syncthreads();
#pragma unroll
        for (int k = 0; k < 16; k++) {
            float ar[4], br[4];
#pragma unroll
            for (int i = 0; i < 4; i++) ar[i] = As[k][ty * 4 + i];
#pragma unroll
            for (int j = 0; j < 4; j++) br[j] = Bs[k][tx * 4 + j];
#pragma unroll
            for (int i = 0; i < 4; i++)
#pragma unroll
                for (int j = 0; j < 4; j++) acc[i][j] = fmaf(ar[i], br[j], acc[i][j]);
        }
        __syncthreads();
    }
#pragma unroll
    for (int i = 0; i < 4; i++) {
        int r = bm + ty * 4 + i;
        if (r < M) {
#pragma unroll
            for (int j = 0; j < 4; j++) C[(size_t)r * Nc + bn + tx * 4 + j] = acc[i][j];
        }
    }
}

// ---------------- per-node attention coefficients ----------------
// reads g_bufA; writes g_als / g_ald.
__global__ void al_kernel(const float* as, const float* ad, int N, int H, int C) {
    int gw = (blockIdx.x * blockDim.x + threadIdx.x) >> 5;
    int lane = threadIdx.x & 31;
    int n = gw / H;
    int hd = gw % H;
    if (n >= N) return;
    size_t base = (size_t)n * H * C + (size_t)hd * C;
    float s1 = 0.f, s2 = 0.f;
    for (int c = lane; c < C; c += 32) {
        float v = g_bufA[base + c];
        s1 = fmaf(v, as[hd * C + c], s1);
        s2 = fmaf(v, ad[hd * C + c], s2);
    }
#pragma unroll
    for (int o = 16; o; o >>= 1) {
        s1 += __shfl_down_sync(0xffffffffu, s1, o);
        s2 += __shfl_down_sync(0xffffffffu, s2, o);
    }
    if (lane == 0) {
        g_als[n * H + hd] = s1;
        g_ald[n * H + hd] = s2;
    }
}

// ---------------- GAT aggregation (block per dst node) ----------------
// reads g_bufA/g_als/g_ald/g_csr/g_off; writes g_bufB. blockDim = H*C.
template <int H, int C>
__global__ void agg_kernel(const float* bias, int applyElu) {
    const int D = H * C;
    const int CHUNK = 64;
    int n = blockIdx.x;
    int t = threadIdx.x;
    __shared__ float sh_m[H];
    __shared__ float sh_iz[H];
    __shared__ float sh_alpha[CHUNK * H];
    __shared__ int sh_src[CHUNK];

    int o0 = g_off[n];
    int deg = g_off[n + 1] - o0;
    int wid = t >> 5, lane = t & 31;

    // pass 1: online softmax (m, z) per head; warp w handles head w
    if (wid < H) {
        int hd = wid;
        float adn = g_ald[n * H + hd];
        float m = -1e30f, s = 0.f;
        for (int j = lane; j <= deg; j += 32) {
            int src = (j < deg) ? g_csr[o0 + j] : n;
            float att = g_als[src * H + hd] + adn;
            att = att > 0.f ? att : 0.2f * att;
            float mn = fmaxf(m, att);
            s = s * __expf(m - mn) + __expf(att - mn);
            m = mn;
        }
#pragma unroll
        for (int o = 16; o; o >>= 1) {
            float m2 = __shfl_down_sync(0xffffffffu, m, o);
            float s2 = __shfl_down_sync(0xffffffffu, s, o);
            float mn = fmaxf(m, m2);
            s = s * __expf(m - mn) + s2 * __expf(m2 - mn);
            m = mn;
        }
        if (lane == 0) {
            sh_m[hd] = m;
            sh_iz[hd] = 1.0f / s;
        }
    }
    __syncthreads();

    // pass 2: chunked alpha staging + weighted accumulation
    int head = t / C;
    float acc = 0.f;
    int total = deg + 1;
    for (int base = 0; base < total; base += CHUNK) {
        int cnt = min(CHUNK, total - base);
        if (t < CHUNK * H) {
            int j = t / H;
            int hd = t % H;
            if (j < cnt) {
                int src = (base + j < deg) ? g_csr[o0 + base + j] : n;
                if (hd == 0) sh_src[j] = src;
                float att = g_als[src * H + hd] + g_ald[n * H + hd];
                att = att > 0.f ? att : 0.2f * att;
                sh_alpha[j * H + hd] = __expf(att - sh_m[hd]) * sh_iz[hd];
            }
        }
        __syncthreads();
#pragma unroll 4
        for (int j = 0; j < cnt; j++) {
            acc = fmaf(g_bufA[(size_t)sh_src[j] * D + t], sh_alpha[j * H + head], acc);
        }
        __syncthreads();
    }
    float r = acc + bias[t];
    if (applyElu) r = r > 0.f ? r : expm1f(r);
    g_bufB[(size_t)n * D + t] = r;
}

// ---------------- edge MLP (warp per edge), factorized layer 1 ----------------
// reads g_prow/g_pcol.
__global__ void edge_mlp_kernel(const int* ei, const float* ea,
                                const float* mw1, const float* mb1,
                                const float* mw2, const float* mb2,
                                const float* mw3, const float* mb3,
                                float* out, int E) {
    int warp = (int)((blockIdx.x * (size_t)blockDim.x + threadIdx.x) >> 5);
    int lane = threadIdx.x & 31;
    if (warp >= E) return;
    int row = ei[warp];
    int col = ei[E + warp];
    float ea0 = ea[warp * 2 + 0];
    float ea1 = ea[warp * 2 + 1];

    // hidden layer 1: 64 outputs, 2 per lane (j = lane, lane+32)
    int j0 = lane, j1 = lane + 32;
    float o1a = g_prow[(size_t)row * 64 + j0] + g_pcol[(size_t)col * 64 + j0]
              + ea0 * mw1[256 * 64 + j0] + ea1 * mw1[257 * 64 + j0] + mb1[j0];
    float o1b = g_prow[(size_t)row * 64 + j1] + g_pcol[(size_t)col * 64 + j1]
              + ea0 * mw1[256 * 64 + j1] + ea1 * mw1[257 * 64 + j1] + mb1[j1];
    o1a = fmaxf(o1a, 0.f);
    o1b = fmaxf(o1b, 0.f);

    // hidden layer 2: lane computes output k = lane (32 outputs)
    float acc = mb2[lane];
#pragma unroll
    for (int j = 0; j < 32; j++) {
        float va = __shfl_sync(0xffffffffu, o1a, j);
        float vb = __shfl_sync(0xffffffffu, o1b, j);
        acc = fmaf(va, mw2[j * 32 + lane], acc);
        acc = fmaf(vb, mw2[(j + 32) * 32 + lane], acc);
    }
    acc = fmaxf(acc, 0.f);

    // output layer
    float v = acc * mw3[lane];
#pragma unroll
    for (int o = 16; o; o >>= 1) v += __shfl_down_sync(0xffffffffu, v, o);
    if (lane == 0) out[warp] = v + mb3[0];
}

// ---------------- launch ----------------
extern "C" void kernel_launch(void* const* d_in, const int* in_sizes, int n_in,
                              void* d_out, int out_size) {
    const float* x = (const float*)d_in[0];
    const int* ei = (const int*)d_in[1];       // int32 (JAX demotes int64)
    const float* ea = (const float*)d_in[2];
    const float* W1 = (const float*)d_in[3];
    const float* a1s = (const float*)d_in[4];
    const float* a1d = (const float*)d_in[5];
    const float* b1 = (const float*)d_in[6];
    const float* W2 = (const float*)d_in[7];
    const float* a2s = (const float*)d_in[8];
    const float* a2d = (const float*)d_in[9];
    const float* b2 = (const float*)d_in[10];
    const float* W3 = (const float*)d_in[11];
    const float* a3s = (const float*)d_in[12];
    const float* a3d = (const float*)d_in[13];
    const float* b3 = (const float*)d_in[14];
    const float* mw1 = (const float*)d_in[15];
    const float* mb1 = (const float*)d_in[16];
    const float* mw2 = (const float*)d_in[17];
    const float* mb2 = (const float*)d_in[18];
    const float* mw3 = (const float*)d_in[19];
    const float* mb3 = (const float*)d_in[20];
    float* out = (float*)d_out;

    int N = in_sizes[0] / 32;
    int E = in_sizes[1] / 2;

    // ---- CSR build (by dst) ----
    zero_deg_kernel<<<(N + 255) / 256, 256>>>(N);
    hist_kernel<<<(E + 255) / 256, 256>>>(ei, E);
    scan_kernel<<<1, 1024>>>(N);
    scatter_kernel<<<(E + 255) / 256, 256>>>(ei, E);

    dim3 g1(256 / 64, (N + 63) / 64);
    dim3 g2(128 / 64, (N + 63) / 64);
    dim3 g3(64 / 64, (N + 63) / 64);

    int alBlocks4 = ((N * 4) * 32 + 255) / 256;
    int alBlocks1 = ((N * 1) * 32 + 255) / 256;

    // ---- layer 1 ----
    gemm64_kernel<false, 0><<<g1, 256>>>(x, W1, N, 32, 256);   // x -> g_bufA
    al_kernel<<<alBlocks4, 256>>>(a1s, a1d, N, 4, 64);
    agg_kernel<4, 64><<<N, 256>>>(b1, 1);                      // g_bufA -> g_bufB

    // ---- layer 2 ----
    gemm64_kernel<true, 0><<<g1, 256>>>(x, W2, N, 256, 256);   // g_bufB -> g_bufA
    al_kernel<<<alBlocks4, 256>>>(a2s, a2d, N, 4, 64);
    agg_kernel<4, 64><<<N, 256>>>(b2, 1);

    // ---- layer 3 (1 head, 128 ch, no ELU) ----
    gemm64_kernel<true, 0><<<g2, 256>>>(x, W3, N, 256, 128);
    al_kernel<<<alBlocks1, 256>>>(a3s, a3d, N, 1, 128);
    agg_kernel<1, 128><<<N, 128>>>(b3, 0);

    // ---- edge MLP precompute: p_row = h3 @ mw1[0:128,:], p_col = h3 @ mw1[128:256,:] ----
    gemm64_kernel<true, 1><<<g3, 256>>>(x, mw1, N, 128, 64);
    gemm64_kernel<true, 2><<<g3, 256>>>(x, mw1 + 128 * 64, N, 128, 64);

    // ---- edge MLP ----
    int warpsPerBlock = 8;
    int blocks = (E + warpsPerBlock - 1) / warpsPerBlock;
    edge_mlp_kernel<<<blocks, warpsPerBlock * 32>>>(ei, ea, mw1, mb1, mw2,
                                                    mb2, mw3, mb3, out, E);
}